// round 14
// baseline (speedup 1.0000x reference)
#include <cuda_runtime.h>

#define N_NODES 100000
#define N_REL 3
#define E_REL 800000
#define E_DEC 500000
#define D 64
#define M_BUCKETS (N_REL * N_NODES)          // 300000
#define E_TOT (N_REL * E_REL)                // 2400000
#define SCAN_BS 512
#define N_SCAN_BLK ((M_BUCKETS + SCAN_BS - 1) / SCAN_BS)  // 586

typedef unsigned long long ull;

// ---- scratch (__device__ globals; no allocs allowed) ----
__device__ float g_ns[M_BUCKETS];
__device__ float g_nd[M_BUCKETS];
__device__ int   g_odeg[M_BUCKETS];
__device__ int   g_ideg[M_BUCKETS];
__device__ int   g_off[M_BUCKETS + 1];
__device__ int   g_cur[M_BUCKETS];
__device__ int   g_bsum[1024];
__device__ int   g_esrc[E_TOT];                  // src-only records, 9.6 MB
__device__ float g_ts[(size_t)N_NODES * D];      // 25.6 MB, per-relation staging (L2-hot)
__device__ float g_h1[(size_t)N_NODES * D];      // 25.6 MB
__device__ float g_h2[(size_t)N_NODES * D];      // 25.6 MB

__global__ void k_zero_deg() {
    int i = blockIdx.x * blockDim.x + threadIdx.x;
    if (i < M_BUCKETS) { g_odeg[i] = 0; g_ideg[i] = 0; }
}

__global__ void k_degree(const int* __restrict__ edges) {
    int t = blockIdx.x * blockDim.x + threadIdx.x;
    if (t >= E_TOT) return;
    int r = t / E_REL;
    int e = t - r * E_REL;
    int s = edges[(r * 2 + 0) * E_REL + e];
    int d = edges[(r * 2 + 1) * E_REL + e];
    atomicAdd(&g_odeg[r * N_NODES + s], 1);
    atomicAdd(&g_ideg[r * N_NODES + d], 1);
}

__global__ void k_norm() {
    int i = blockIdx.x * blockDim.x + threadIdx.x;
    if (i < M_BUCKETS) {
        g_ns[i] = rsqrtf((float)max(g_odeg[i], 1));
        g_nd[i] = rsqrtf((float)max(g_ideg[i], 1));
    }
}

// ---- 3-pass exclusive prefix scan of g_ideg -> g_off ----
__global__ void k_scan_a() {
    int i = blockIdx.x * SCAN_BS + threadIdx.x;
    int v = (i < M_BUCKETS) ? g_ideg[i] : 0;
    int lane = threadIdx.x & 31, wid = threadIdx.x >> 5;
    int inc = v;
#pragma unroll
    for (int o = 1; o < 32; o <<= 1) {
        int t = __shfl_up_sync(0xffffffffu, inc, o);
        if (lane >= o) inc += t;
    }
    __shared__ int wsum[SCAN_BS / 32];
    if (lane == 31) wsum[wid] = inc;
    __syncthreads();
    if (wid == 0) {
        int s = (lane < SCAN_BS / 32) ? wsum[lane] : 0;
#pragma unroll
        for (int o = 1; o < SCAN_BS / 32; o <<= 1) {
            int t = __shfl_up_sync(0xffffffffu, s, o);
            if (lane >= o) s += t;
        }
        if (lane < SCAN_BS / 32) wsum[lane] = s;
    }
    __syncthreads();
    int excl = inc - v + (wid > 0 ? wsum[wid - 1] : 0);
    if (i < M_BUCKETS) g_off[i] = excl;
    if (threadIdx.x == SCAN_BS - 1) g_bsum[blockIdx.x] = excl + v;
}

__global__ void k_scan_b() {
    int tid = threadIdx.x;                  // 1024 threads
    int v = (tid < N_SCAN_BLK) ? g_bsum[tid] : 0;
    int lane = tid & 31, wid = tid >> 5;
    int inc = v;
#pragma unroll
    for (int o = 1; o < 32; o <<= 1) {
        int t = __shfl_up_sync(0xffffffffu, inc, o);
        if (lane >= o) inc += t;
    }
    __shared__ int wsum[32];
    if (lane == 31) wsum[wid] = inc;
    __syncthreads();
    if (wid == 0) {
        int s = (lane < 32) ? wsum[lane] : 0;
#pragma unroll
        for (int o = 1; o < 32; o <<= 1) {
            int t = __shfl_up_sync(0xffffffffu, s, o);
            if (lane >= o) s += t;
        }
        wsum[lane] = s;
    }
    __syncthreads();
    int excl = inc - v + (wid > 0 ? wsum[wid - 1] : 0);
    if (tid < N_SCAN_BLK) g_bsum[tid] = excl;
}

__global__ void k_scan_c() {
    int i = blockIdx.x * blockDim.x + threadIdx.x;
    if (i < M_BUCKETS) {
        int off = g_off[i] + g_bsum[i / SCAN_BS];
        g_off[i] = off;
        g_cur[i] = off;
    }
    if (i == 0) g_off[M_BUCKETS] = E_TOT;
}

__global__ void k_fill(const int* __restrict__ edges) {
    int t = blockIdx.x * blockDim.x + threadIdx.x;
    if (t >= E_TOT) return;
    int r = t / E_REL;
    int e = t - r * E_REL;
    int s = edges[(r * 2 + 0) * E_REL + e];
    int d = edges[(r * 2 + 1) * E_REL + e];
    int pos = atomicAdd(&g_cur[r * N_NODES + d], 1);
    g_esrc[pos] = s;          // src only: ns[src] is applied in k_mlp1
}

// ---- Single-relation GEMM: g_ts[n] = (in[n] * ns_r[n]) @ W_r
// Thread-per-node, row in registers, FFMA2-packed (proven R4 structure).
__global__ void __launch_bounds__(128) k_mlp1(const float* __restrict__ in,
                                              const float* __restrict__ W,
                                              int r) {
    __shared__ float sW[D * D];  // 16 KB
    for (int i = threadIdx.x; i < D * D / 4; i += 128)
        reinterpret_cast<float4*>(sW)[i] = reinterpret_cast<const float4*>(W)[i];
    __syncthreads();

    int n = blockIdx.x * 128 + threadIdx.x;
    if (n >= N_NODES) return;

    float scale = g_ns[r * N_NODES + n];
    const float4* xr = reinterpret_cast<const float4*>(in + (size_t)n * D);

    ull acc[D / 2];
#pragma unroll
    for (int i = 0; i < D / 2; i++) acc[i] = 0ull;

#pragma unroll
    for (int i4 = 0; i4 < D / 4; i4++) {
        float4 a = xr[i4];
        float av[4] = {a.x * scale, a.y * scale, a.z * scale, a.w * scale};
#pragma unroll
        for (int k = 0; k < 4; k++) {
            ull av2;
            asm("mov.b64 %0, {%1, %1};" : "=l"(av2) : "f"(av[k]));
            const ull* wrow = reinterpret_cast<const ull*>(sW + (i4 * 4 + k) * D);
#pragma unroll
            for (int jp = 0; jp < D / 2; jp++) {
                asm("fma.rn.f32x2 %0, %1, %2, %0;"
                    : "+l"(acc[jp]) : "l"(av2), "l"(wrow[jp]));
            }
        }
    }

    float4* trow = reinterpret_cast<float4*>(g_ts + (size_t)n * D);
#pragma unroll
    for (int q = 0; q < D / 4; q++) {
        float v0, v1, v2, v3;
        asm("mov.b64 {%0, %1}, %2;" : "=f"(v0), "=f"(v1) : "l"(acc[2 * q]));
        asm("mov.b64 {%0, %1}, %2;" : "=f"(v2), "=f"(v3) : "l"(acc[2 * q + 1]));
        trow[q] = make_float4(v0, v1, v2, v3);
    }
}

// ---- Single-relation batched CSR pull from g_ts (fully L2-resident).
// h[d] (+)= nd_r[d] * sum_e g_ts[src_e];   last pass adds bias (+relu).
__global__ void __launch_bounds__(256) k_agg1(float* __restrict__ hout,
                                              const float* __restrict__ b,
                                              int r, int first, int last,
                                              int do_relu) {
    __shared__ float sb[D];
    if (last && threadIdx.x < D)
        sb[threadIdx.x] = b[threadIdx.x] + b[D + threadIdx.x] + b[2 * D + threadIdx.x];
    if (last) __syncthreads();

    int d = blockIdx.x * 8 + (threadIdx.x >> 5);   // 12500*8 = 100000 exact
    int lane = threadIdx.x & 31;
    int col = lane * 2;

    int m = r * N_NODES + d;
    int start = g_off[m], end = g_off[m + 1];
    float ax = 0.f, ay = 0.f;

    for (int base = start; base < end; base += 32) {
        int cnt = min(32, end - base);
        int sidx = 0;
        if (base + lane < end) sidx = g_esrc[base + lane];

        for (int j = 0; j < cnt; j += 8) {
            float vx[8], vy[8];
#pragma unroll
            for (int u = 0; u < 8; u++) {
                int k = j + u;
                if (k < cnt) {              // warp-uniform
                    int ss = __shfl_sync(0xffffffffu, sidx, k);
                    float2 v = *reinterpret_cast<const float2*>(
                        g_ts + (size_t)ss * D + col);
                    vx[u] = v.x; vy[u] = v.y;
                } else { vx[u] = 0.f; vy[u] = 0.f; }
            }
#pragma unroll
            for (int u = 0; u < 8; u++) {
                ax += vx[u];
                ay += vy[u];
            }
        }
    }

    float ndv = g_nd[m];
    float2 tot = make_float2(ax * ndv, ay * ndv);
    float* hp = hout + (size_t)d * D + col;
    if (!first) {
        float2 prev = *reinterpret_cast<const float2*>(hp);
        tot.x += prev.x; tot.y += prev.y;
    }
    if (last) {
        tot.x += sb[col]; tot.y += sb[col + 1];
        if (do_relu) { tot.x = fmaxf(tot.x, 0.f); tot.y = fmaxf(tot.y, 0.f); }
    }
    *reinterpret_cast<float2*>(hp) = tot;
}

// ---- Edge scorer: one warp per dec edge ----
__global__ void __launch_bounds__(256) k_decoder(const int* __restrict__ dec,
                                                 const float* __restrict__ Wp,
                                                 const float* __restrict__ bp,
                                                 float* __restrict__ out) {
    __shared__ float sW[2 * D * N_REL];
    __shared__ float sb[N_REL];
    for (int i = threadIdx.x; i < 2 * D * N_REL; i += blockDim.x) sW[i] = Wp[i];
    if (threadIdx.x < N_REL) sb[threadIdx.x] = bp[threadIdx.x];
    __syncthreads();

    int e = blockIdx.x * 8 + (threadIdx.x >> 5);
    if (e >= E_DEC) return;
    int lane = threadIdx.x & 31;
    int s = dec[e];
    int d = dec[E_DEC + e];
    float2 a  = *reinterpret_cast<const float2*>(g_h2 + (size_t)s * D + lane * 2);
    float2 bb = *reinterpret_cast<const float2*>(g_h2 + (size_t)d * D + lane * 2);

    int j0 = lane * 2;
    float p0, p1, p2;
    p0 = a.x  * sW[(j0 + 0) * 3 + 0] + a.y  * sW[(j0 + 1) * 3 + 0]
       + bb.x * sW[(D + j0 + 0) * 3 + 0] + bb.y * sW[(D + j0 + 1) * 3 + 0];
    p1 = a.x  * sW[(j0 + 0) * 3 + 1] + a.y  * sW[(j0 + 1) * 3 + 1]
       + bb.x * sW[(D + j0 + 0) * 3 + 1] + bb.y * sW[(D + j0 + 1) * 3 + 1];
    p2 = a.x  * sW[(j0 + 0) * 3 + 2] + a.y  * sW[(j0 + 1) * 3 + 2]
       + bb.x * sW[(D + j0 + 0) * 3 + 2] + bb.y * sW[(D + j0 + 1) * 3 + 2];

#pragma unroll
    for (int off = 16; off; off >>= 1) {
        p0 += __shfl_xor_sync(0xffffffffu, p0, off);
        p1 += __shfl_xor_sync(0xffffffffu, p1, off);
        p2 += __shfl_xor_sync(0xffffffffu, p2, off);
    }
    if (lane == 0) {
        out[(size_t)e * 3 + 0] = p0 + sb[0];
        out[(size_t)e * 3 + 1] = p1 + sb[1];
        out[(size_t)e * 3 + 2] = p2 + sb[2];
    }
}

extern "C" void kernel_launch(void* const* d_in, const int* in_sizes, int n_in,
                              void* d_out, int out_size) {
    (void)in_sizes; (void)n_in; (void)out_size;
    const float* x    = (const float*)d_in[0];
    const int*   edges= (const int*)d_in[1];
    const int*   dec  = (const int*)d_in[2];
    const float* W1   = (const float*)d_in[3];
    const float* b1   = (const float*)d_in[4];
    const float* W2   = (const float*)d_in[5];
    const float* b2   = (const float*)d_in[6];
    const float* Wp   = (const float*)d_in[7];
    const float* bp   = (const float*)d_in[8];
    float* out = (float*)d_out;

    void *p_h1 = nullptr, *p_h2 = nullptr;
    cudaGetSymbolAddress(&p_h1, g_h1);
    cudaGetSymbolAddress(&p_h2, g_h2);
    float* h1 = (float*)p_h1;
    float* h2 = (float*)p_h2;

    const int TB = 256;
    // degrees + norms (edges identical for both layers)
    k_zero_deg<<<(M_BUCKETS + TB - 1) / TB, TB>>>();
    k_degree<<<(E_TOT + TB - 1) / TB, TB>>>(edges);
    k_norm<<<(M_BUCKETS + TB - 1) / TB, TB>>>();

    // CSR build (src-only records); reused by both layers
    k_scan_a<<<N_SCAN_BLK, SCAN_BS>>>();
    k_scan_b<<<1, 1024>>>();
    k_scan_c<<<(M_BUCKETS + TB - 1) / TB, TB>>>();
    k_fill<<<(E_TOT + TB - 1) / TB, TB>>>(edges);

    int mgrid = (N_NODES + 127) / 128;       // 782
    int agrid = N_NODES / 8;                 // 12500 exact

    // layer 1: relation-sliced pipeline, ts stays L2-resident
    for (int r = 0; r < N_REL; r++) {
        k_mlp1<<<mgrid, 128>>>(x, W1 + (size_t)r * D * D, r);
        k_agg1<<<agrid, TB>>>(h1, b1, r, r == 0, r == N_REL - 1, 1);
    }
    // layer 2
    for (int r = 0; r < N_REL; r++) {
        k_mlp1<<<mgrid, 128>>>(h1, W2 + (size_t)r * D * D, r);
        k_agg1<<<agrid, TB>>>(h2, b2, r, r == 0, r == N_REL - 1, 0);
    }

    // decoder
    k_decoder<<<(E_DEC + 7) / 8, TB>>>(dec, Wp, bp, out);
}

// round 16
// speedup vs baseline: 1.1797x; 1.1797x over previous
#include <cuda_runtime.h>

#define N_NODES 100000
#define N_REL 3
#define E_REL 800000
#define E_DEC 500000
#define D 64
#define M_BUCKETS (N_REL * N_NODES)          // 300000
#define E_TOT (N_REL * E_REL)                // 2400000
#define SCAN_BS 512
#define N_SCAN_BLK ((M_BUCKETS + SCAN_BS - 1) / SCAN_BS)  // 586

typedef unsigned long long ull;

// ---- scratch (__device__ globals; no allocs allowed) ----
__device__ float g_ns[M_BUCKETS];
__device__ float g_nd[M_BUCKETS];
__device__ int   g_odeg[M_BUCKETS];
__device__ int   g_ideg[M_BUCKETS];
__device__ int   g_off[M_BUCKETS + 1];
__device__ int   g_cur[M_BUCKETS];
__device__ int   g_bsum[1024];
__device__ ull   g_epack[E_TOT];                 // (ns[src]<<32)|src, 19.2 MB
__device__ float g_t[(size_t)N_REL * N_NODES * D];  // 76.8 MB (aggregated rows)
__device__ float g_h1[(size_t)N_NODES * D];      // 25.6 MB
__device__ float g_h2[(size_t)N_NODES * D];      // 25.6 MB

__global__ void k_zero_deg() {
    int i = blockIdx.x * blockDim.x + threadIdx.x;
    if (i < M_BUCKETS) { g_odeg[i] = 0; g_ideg[i] = 0; }
}

__global__ void k_degree(const int* __restrict__ edges) {
    int t = blockIdx.x * blockDim.x + threadIdx.x;
    if (t >= E_TOT) return;
    int r = t / E_REL;
    int e = t - r * E_REL;
    int s = edges[(r * 2 + 0) * E_REL + e];
    int d = edges[(r * 2 + 1) * E_REL + e];
    atomicAdd(&g_odeg[r * N_NODES + s], 1);
    atomicAdd(&g_ideg[r * N_NODES + d], 1);
}

__global__ void k_norm() {
    int i = blockIdx.x * blockDim.x + threadIdx.x;
    if (i < M_BUCKETS) {
        g_ns[i] = rsqrtf((float)max(g_odeg[i], 1));
        g_nd[i] = rsqrtf((float)max(g_ideg[i], 1));
    }
}

// ---- 3-pass exclusive prefix scan of g_ideg -> g_off ----
__global__ void k_scan_a() {
    int i = blockIdx.x * SCAN_BS + threadIdx.x;
    int v = (i < M_BUCKETS) ? g_ideg[i] : 0;
    int lane = threadIdx.x & 31, wid = threadIdx.x >> 5;
    int inc = v;
#pragma unroll
    for (int o = 1; o < 32; o <<= 1) {
        int t = __shfl_up_sync(0xffffffffu, inc, o);
        if (lane >= o) inc += t;
    }
    __shared__ int wsum[SCAN_BS / 32];
    if (lane == 31) wsum[wid] = inc;
    __syncthreads();
    if (wid == 0) {
        int s = (lane < SCAN_BS / 32) ? wsum[lane] : 0;
#pragma unroll
        for (int o = 1; o < SCAN_BS / 32; o <<= 1) {
            int t = __shfl_up_sync(0xffffffffu, s, o);
            if (lane >= o) s += t;
        }
        if (lane < SCAN_BS / 32) wsum[lane] = s;
    }
    __syncthreads();
    int excl = inc - v + (wid > 0 ? wsum[wid - 1] : 0);
    if (i < M_BUCKETS) g_off[i] = excl;
    if (threadIdx.x == SCAN_BS - 1) g_bsum[blockIdx.x] = excl + v;
}

__global__ void k_scan_b() {
    int tid = threadIdx.x;                  // 1024 threads
    int v = (tid < N_SCAN_BLK) ? g_bsum[tid] : 0;
    int lane = tid & 31, wid = tid >> 5;
    int inc = v;
#pragma unroll
    for (int o = 1; o < 32; o <<= 1) {
        int t = __shfl_up_sync(0xffffffffu, inc, o);
        if (lane >= o) inc += t;
    }
    __shared__ int wsum[32];
    if (lane == 31) wsum[wid] = inc;
    __syncthreads();
    if (wid == 0) {
        int s = (lane < 32) ? wsum[lane] : 0;
#pragma unroll
        for (int o = 1; o < 32; o <<= 1) {
            int t = __shfl_up_sync(0xffffffffu, s, o);
            if (lane >= o) s += t;
        }
        wsum[lane] = s;
    }
    __syncthreads();
    int excl = inc - v + (wid > 0 ? wsum[wid - 1] : 0);
    if (tid < N_SCAN_BLK) g_bsum[tid] = excl;
}

__global__ void k_scan_c() {
    int i = blockIdx.x * blockDim.x + threadIdx.x;
    if (i < M_BUCKETS) {
        int off = g_off[i] + g_bsum[i / SCAN_BS];
        g_off[i] = off;
        g_cur[i] = off;
    }
    if (i == 0) g_off[M_BUCKETS] = E_TOT;
}

__global__ void k_fill(const int* __restrict__ edges) {
    int t = blockIdx.x * blockDim.x + threadIdx.x;
    if (t >= E_TOT) return;
    int r = t / E_REL;
    int e = t - r * E_REL;
    int s = edges[(r * 2 + 0) * E_REL + e];
    int d = edges[(r * 2 + 1) * E_REL + e];
    float c = g_ns[r * N_NODES + s];          // src-norm rides with the record
    int pos = atomicAdd(&g_cur[r * N_NODES + d], 1);
    g_epack[pos] = ((ull)__float_as_uint(c) << 32) | (unsigned)s;
}

// ---- CSR pull aggregation from `feat` (25.6 MB, L2-resident). R4-proven shape:
// warp per dst; 16 lanes x float4 cover the row; 2 halves = 2 independent chains;
// record prefetch pipelines the idx->gather dependency.
// g_t[(r,d)] = nd_r[d] * sum_e ns[src_e] * feat[src_e]
__global__ void __launch_bounds__(256) k_agg(const float* __restrict__ feat) {
    int d = blockIdx.x * 8 + (threadIdx.x >> 5);   // 12500*8 = 100000 exact
    int lane = threadIdx.x & 31;
    int j = (lane & 15) * 4;
    int half = lane >> 4;

#pragma unroll
    for (int r = 0; r < N_REL; r++) {
        int m = r * N_NODES + d;
        int start = g_off[m], end = g_off[m + 1];
        float4 acc = make_float4(0.f, 0.f, 0.f, 0.f);

        int i = start + half;
        ull pk = (i < end) ? g_epack[i] : 0;
        for (; i < end; i += 2) {
            ull cur = pk;
            if (i + 2 < end) pk = g_epack[i + 2];      // prefetch next record
            int   ss = (int)(unsigned)(cur & 0xffffffffu);
            float c  = __uint_as_float((unsigned)(cur >> 32));
            float4 v = *reinterpret_cast<const float4*>(feat + (size_t)ss * D + j);
            acc.x += v.x * c; acc.y += v.y * c;
            acc.z += v.z * c; acc.w += v.w * c;
        }

        // combine the two halves (lane L with L+16; same column j)
        acc.x += __shfl_xor_sync(0xffffffffu, acc.x, 16);
        acc.y += __shfl_xor_sync(0xffffffffu, acc.y, 16);
        acc.z += __shfl_xor_sync(0xffffffffu, acc.z, 16);
        acc.w += __shfl_xor_sync(0xffffffffu, acc.w, 16);

        if (half == 0) {
            float ndv = g_nd[m];
            acc.x *= ndv; acc.y *= ndv; acc.z *= ndv; acc.w *= ndv;
            *reinterpret_cast<float4*>(g_t + (size_t)m * D + j) = acc;
        }
    }
}

// ---- Combine MLP (R12-proven): out[n] = (relu?)(sum_r g_t[(r,n)] @ W_r + sum b_r)
// Thread-per-node, rows read once, FFMA2-packed.
__global__ void __launch_bounds__(128) k_mlp(float* __restrict__ out,
                                             const float* __restrict__ W,
                                             const float* __restrict__ b,
                                             int do_relu) {
    __shared__ float sW[D * D];  // 16 KB, per relation
    __shared__ float sb[D];
    if (threadIdx.x < D)
        sb[threadIdx.x] = b[threadIdx.x] + b[D + threadIdx.x] + b[2 * D + threadIdx.x];
    int n = blockIdx.x * 128 + threadIdx.x;

    ull acc[D / 2];
#pragma unroll
    for (int i = 0; i < D / 2; i++) acc[i] = 0ull;

    for (int r = 0; r < N_REL; r++) {
        __syncthreads();
        for (int i = threadIdx.x; i < D * D / 4; i += 128)
            reinterpret_cast<float4*>(sW)[i] =
                reinterpret_cast<const float4*>(W + r * D * D)[i];
        __syncthreads();

        if (n < N_NODES) {
            const float4* arow = reinterpret_cast<const float4*>(
                g_t + ((size_t)r * N_NODES + n) * D);
#pragma unroll
            for (int i4 = 0; i4 < D / 4; i4++) {
                float4 a = arow[i4];
                float av[4] = {a.x, a.y, a.z, a.w};
#pragma unroll
                for (int k = 0; k < 4; k++) {
                    ull av2;
                    asm("mov.b64 %0, {%1, %1};" : "=l"(av2) : "f"(av[k]));
                    const ull* wrow = reinterpret_cast<const ull*>(
                        sW + (i4 * 4 + k) * D);
#pragma unroll
                    for (int jp = 0; jp < D / 2; jp++) {
                        asm("fma.rn.f32x2 %0, %1, %2, %0;"
                            : "+l"(acc[jp]) : "l"(av2), "l"(wrow[jp]));
                    }
                }
            }
        }
    }

    if (n < N_NODES) {
        float4* orow = reinterpret_cast<float4*>(out + (size_t)n * D);
#pragma unroll
        for (int q = 0; q < D / 4; q++) {
            float v0, v1, v2, v3;
            asm("mov.b64 {%0, %1}, %2;" : "=f"(v0), "=f"(v1) : "l"(acc[2 * q]));
            asm("mov.b64 {%0, %1}, %2;" : "=f"(v2), "=f"(v3) : "l"(acc[2 * q + 1]));
            int j = 4 * q;
            v0 += sb[j + 0]; v1 += sb[j + 1]; v2 += sb[j + 2]; v3 += sb[j + 3];
            if (do_relu) {
                v0 = fmaxf(v0, 0.f); v1 = fmaxf(v1, 0.f);
                v2 = fmaxf(v2, 0.f); v3 = fmaxf(v3, 0.f);
            }
            orow[q] = make_float4(v0, v1, v2, v3);
        }
    }
}

// ---- Edge scorer: one warp per dec edge ----
__global__ void __launch_bounds__(256) k_decoder(const int* __restrict__ dec,
                                                 const float* __restrict__ Wp,
                                                 const float* __restrict__ bp,
                                                 float* __restrict__ out) {
    __shared__ float sW[2 * D * N_REL];
    __shared__ float sb[N_REL];
    for (int i = threadIdx.x; i < 2 * D * N_REL; i += blockDim.x) sW[i] = Wp[i];
    if (threadIdx.x < N_REL) sb[threadIdx.x] = bp[threadIdx.x];
    __syncthreads();

    int e = blockIdx.x * 8 + (threadIdx.x >> 5);
    if (e >= E_DEC) return;
    int lane = threadIdx.x & 31;
    int s = dec[e];
    int d = dec[E_DEC + e];
    float2 a  = *reinterpret_cast<const float2*>(g_h2 + (size_t)s * D + lane * 2);
    float2 bb = *reinterpret_cast<const float2*>(g_h2 + (size_t)d * D + lane * 2);

    int j0 = lane * 2;
    float p0, p1, p2;
    p0 = a.x  * sW[(j0 + 0) * 3 + 0] + a.y  * sW[(j0 + 1) * 3 + 0]
       + bb.x * sW[(D + j0 + 0) * 3 + 0] + bb.y * sW[(D + j0 + 1) * 3 + 0];
    p1 = a.x  * sW[(j0 + 0) * 3 + 1] + a.y  * sW[(j0 + 1) * 3 + 1]
       + bb.x * sW[(D + j0 + 0) * 3 + 1] + bb.y * sW[(D + j0 + 1) * 3 + 1];
    p2 = a.x  * sW[(j0 + 0) * 3 + 2] + a.y  * sW[(j0 + 1) * 3 + 2]
       + bb.x * sW[(D + j0 + 0) * 3 + 2] + bb.y * sW[(D + j0 + 1) * 3 + 2];

#pragma unroll
    for (int off = 16; off; off >>= 1) {
        p0 += __shfl_xor_sync(0xffffffffu, p0, off);
        p1 += __shfl_xor_sync(0xffffffffu, p1, off);
        p2 += __shfl_xor_sync(0xffffffffu, p2, off);
    }
    if (lane == 0) {
        out[(size_t)e * 3 + 0] = p0 + sb[0];
        out[(size_t)e * 3 + 1] = p1 + sb[1];
        out[(size_t)e * 3 + 2] = p2 + sb[2];
    }
}

extern "C" void kernel_launch(void* const* d_in, const int* in_sizes, int n_in,
                              void* d_out, int out_size) {
    (void)in_sizes; (void)n_in; (void)out_size;
    const float* x    = (const float*)d_in[0];
    const int*   edges= (const int*)d_in[1];
    const int*   dec  = (const int*)d_in[2];
    const float* W1   = (const float*)d_in[3];
    const float* b1   = (const float*)d_in[4];
    const float* W2   = (const float*)d_in[5];
    const float* b2   = (const float*)d_in[6];
    const float* Wp   = (const float*)d_in[7];
    const float* bp   = (const float*)d_in[8];
    float* out = (float*)d_out;

    void *p_h1 = nullptr, *p_h2 = nullptr;
    cudaGetSymbolAddress(&p_h1, g_h1);
    cudaGetSymbolAddress(&p_h2, g_h2);
    float* h1 = (float*)p_h1;
    float* h2 = (float*)p_h2;

    const int TB = 256;
    // degrees + norms (edges identical for both layers)
    k_zero_deg<<<(M_BUCKETS + TB - 1) / TB, TB>>>();
    k_degree<<<(E_TOT + TB - 1) / TB, TB>>>(edges);
    k_norm<<<(M_BUCKETS + TB - 1) / TB, TB>>>();

    // CSR build with packed (ns[src], src) records; reused by both layers
    k_scan_a<<<N_SCAN_BLK, SCAN_BS>>>();
    k_scan_b<<<1, 1024>>>();
    k_scan_c<<<(M_BUCKETS + TB - 1) / TB, TB>>>();
    k_fill<<<(E_TOT + TB - 1) / TB, TB>>>(edges);

    int agrid = N_NODES / 8;                 // 12500 exact
    int mgrid = (N_NODES + 127) / 128;       // 782

    // layer 1: agg-first from L2-hot x; then combine GEMM
    k_agg<<<agrid, TB>>>(x);
    k_mlp<<<mgrid, 128>>>(h1, W1, b1, 1);

    // layer 2
    k_agg<<<agrid, TB>>>(h1);
    k_mlp<<<mgrid, 128>>>(h2, W2, b2, 0);

    // decoder
    k_decoder<<<(E_DEC + 7) / 8, TB>>>(dec, Wp, bp, out);
}